// round 12
// baseline (speedup 1.0000x reference)
#include <cuda_runtime.h>
#include <cuda_bf16.h>
#include <cuda_fp16.h>
#include <cstdint>
#include <math.h>

// Problem constants
#define MAXN 100000
#define MAXE 1600000
#define NB_MAX ((MAXN + 1023) / 1024)

// ---------------- device scratch ----------------
// packed bf16x2 split inputs (low 16 bits = even k, high = odd k)
__device__ uint32_t g_A0h[MAXN * 128];  // layer0 input hi  (K=256 -> 128 pairs)
__device__ uint32_t g_A0l[MAXN * 128];  // layer0 input lo
__device__ uint32_t g_Ahh[MAXN * 64];   // relu(h) hi (K=128 -> 64 pairs)
__device__ uint32_t g_Ahl[MAXN * 64];   // relu(h) lo
__device__ uint32_t g_Cq[MAXN * 64];    // h@Wl as packed half2 (aggregation gather source)
__device__ float g_Cr[MAXN * 128];      // h@Wr + b (fp32)
__device__ float g_h[MAXN * 128];       // layer output (pre-activation, fp32 for l3)
__device__ int   g_rowptr[MAXN + 1];
__device__ int   g_col[MAXE];
__device__ int   g_cnt[MAXN];
__device__ int   g_fill[MAXN];
__device__ int   g_bsum[NB_MAX + 2];
__device__ int   g_bscan[NB_MAX + 2];
__device__ float g_p[MAXN];
__device__ float g_r3[MAXN];
__device__ float g_sum[1];
// packed bf16-split weights [kp][n]: per layer: l-hi, l-lo, r-hi, r-lo
__device__ uint32_t g_W0[4 * 128 * 128];
__device__ uint32_t g_W1[4 * 64 * 128];
__device__ uint32_t g_W2[4 * 64 * 128];

// ---------------- helpers ----------------
__device__ __forceinline__ uint32_t smem_u32(const void* p) {
    uint32_t a;
    asm("{ .reg .u64 t; cvta.to.shared.u64 t, %1; cvt.u32.u64 %0, t; }" : "=r"(a) : "l"(p));
    return a;
}
__device__ __forceinline__ void cpa16(uint32_t dst, const void* src, bool pred) {
    int sz = pred ? 16 : 0;
    asm volatile("cp.async.cg.shared.global [%0], [%1], 16, %2;" :: "r"(dst), "l"(src), "r"(sz));
}
__device__ __forceinline__ void cpa_commit() { asm volatile("cp.async.commit_group;"); }
template <int NLeft> __device__ __forceinline__ void cpa_wait() {
    asm volatile("cp.async.wait_group %0;" :: "n"(NLeft));
}
// split two fp32 into packed bf16x2 hi/lo
__device__ __forceinline__ void split2(float a, float b, uint32_t& hi, uint32_t& lo) {
    __nv_bfloat16 ha = __float2bfloat16(a);
    __nv_bfloat16 hb = __float2bfloat16(b);
    float ra = a - __bfloat162float(ha);
    float rb = b - __bfloat162float(hb);
    __nv_bfloat16 la = __float2bfloat16(ra);
    __nv_bfloat16 lb = __float2bfloat16(rb);
    hi = ((uint32_t)__bfloat16_as_ushort(hb) << 16) | __bfloat16_as_ushort(ha);
    lo = ((uint32_t)__bfloat16_as_ushort(lb) << 16) | __bfloat16_as_ushort(la);
}

// ---------------- utility kernels ----------------
__global__ void zero_kernel(int* cnt, int* fill, float* gsum, int Nn) {
    int i = blockIdx.x * blockDim.x + threadIdx.x;
    if (i == 0) *gsum = 0.0f;
    for (; i < Nn; i += gridDim.x * blockDim.x) { cnt[i] = 0; fill[i] = 0; }
}

// concat + bf16-split directly into packed layer0 input
__global__ void concat_kernel(const float* __restrict__ x, const float* __restrict__ d,
                              const float* __restrict__ r, const float* __restrict__ hp,
                              uint32_t* __restrict__ A0h, uint32_t* __restrict__ A0l, int Nn) {
    int idx = blockIdx.x * blockDim.x + threadIdx.x;   // one k-pair per thread
    if (idx < Nn * 128) {
        int n = idx >> 7, kp = idx & 127;
        int seg = kp >> 5, w = kp & 31;
        const float* src = (seg == 0) ? x : (seg == 1) ? d : (seg == 2) ? r : hp;
        float2 v = *(const float2*)&src[(size_t)n * 64 + w * 2];
        uint32_t hi, lo;
        split2(v.x, v.y, hi, lo);
        A0h[idx] = hi;
        A0l[idx] = lo;
    }
}

__global__ void count_kernel(const int* __restrict__ ei, int E, int* __restrict__ cnt) {
    int e = blockIdx.x * blockDim.x + threadIdx.x;
    if (e < E) atomicAdd(&cnt[ei[E + e]], 1);
}

__global__ void scan1_kernel(const int* __restrict__ cnt, int* __restrict__ rowptr,
                             int* __restrict__ bsum, int Nn) {
    __shared__ int ws[32];
    int i = blockIdx.x * 1024 + threadIdx.x;
    int lane = threadIdx.x & 31, wid = threadIdx.x >> 5;
    int v = (i < Nn) ? cnt[i] : 0;
    int x = v;
#pragma unroll
    for (int off = 1; off < 32; off <<= 1) {
        int t = __shfl_up_sync(0xffffffffu, x, off);
        if (lane >= off) x += t;
    }
    if (lane == 31) ws[wid] = x;
    __syncthreads();
    if (wid == 0) {
        int w = ws[lane];
#pragma unroll
        for (int off = 1; off < 32; off <<= 1) {
            int t = __shfl_up_sync(0xffffffffu, w, off);
            if (lane >= off) w += t;
        }
        ws[lane] = w;
    }
    __syncthreads();
    int base = (wid > 0) ? ws[wid - 1] : 0;
    if (i < Nn) rowptr[i] = base + x - v;
    if (threadIdx.x == 1023) bsum[blockIdx.x] = base + x;
}

__global__ void scan2_kernel(const int* __restrict__ bsum, int* __restrict__ bscan, int NB) {
    __shared__ int ws[4];
    int tid = threadIdx.x, lane = tid & 31, wid = tid >> 5;
    int v = (tid < NB) ? bsum[tid] : 0;
    int x = v;
#pragma unroll
    for (int off = 1; off < 32; off <<= 1) {
        int t = __shfl_up_sync(0xffffffffu, x, off);
        if (lane >= off) x += t;
    }
    if (lane == 31) ws[wid] = x;
    __syncthreads();
    int base = 0;
    for (int t = 0; t < wid; t++) base += ws[t];
    if (tid < NB) bscan[tid] = base + x - v;
}

__global__ void scan3_kernel(int* __restrict__ rowptr, const int* __restrict__ bscan,
                             int Nn, int E) {
    int i = blockIdx.x * blockDim.x + threadIdx.x;
    if (i < Nn) rowptr[i] += bscan[i >> 10];
    if (i == 0) rowptr[Nn] = E;
}

__global__ void fill_kernel(const int* __restrict__ ei, int E,
                            const int* __restrict__ rowptr, int* __restrict__ fill,
                            int* __restrict__ colA) {
    int e = blockIdx.x * blockDim.x + threadIdx.x;
    if (e < E) {
        int src = ei[e];
        int dst = ei[E + e];
        int pos = atomicAdd(&fill[dst], 1);
        colA[rowptr[dst] + pos] = src;
    }
}

// weight prep: bf16 split + pack pairs along k; layout [kp][128]
__global__ void prep_w_kernel(const float* __restrict__ W, uint32_t* __restrict__ Hi,
                              uint32_t* __restrict__ Lo, int K2) {
    int idx = blockIdx.x * blockDim.x + threadIdx.x;
    if (idx < K2 * 128) {
        int kp = idx >> 7, n = idx & 127;
        float v0 = W[(size_t)(2 * kp) * 128 + n];
        float v1 = W[(size_t)(2 * kp + 1) * 128 + n];
        uint32_t hi, lo;
        split2(v0, v1, hi, lo);
        Hi[idx] = hi;
        Lo[idx] = lo;
    }
}

// ---------------- bf16x3 split mma.sync GEMM, cp.async double-buffered ----------------
// grid (ceil(N/128), 2): y=0 -> Cq (half2) = A@Wl ; y=1 -> Cr (fp32) = A@Wr + b
// BM=128, BN=128, BK=32 (16 k-pairs); 8 warps 4(m)x2(n); warp tile 32x64; m16n8k16 x3.
#define A_LDp  20                    // uint32 per A row per stage (16 + 4 pad)
#define W_LDp  132
#define A_U    (128 * A_LDp)         // 2560
#define W_U    (16 * W_LDp)          // 2112
#define STAGE_U (2 * A_U + 2 * W_U)  // 9344 uint32
#define GSMEM  (2 * STAGE_U * 4)     // 74752 bytes

__device__ __forceinline__ void mma_bf16(float* d, const uint32_t* a, uint32_t b0, uint32_t b1) {
    asm volatile(
        "mma.sync.aligned.m16n8k16.row.col.f32.bf16.bf16.f32 "
        "{%0,%1,%2,%3}, {%4,%5,%6,%7}, {%8,%9}, {%0,%1,%2,%3};"
        : "+f"(d[0]), "+f"(d[1]), "+f"(d[2]), "+f"(d[3])
        : "r"(a[0]), "r"(a[1]), "r"(a[2]), "r"(a[3]), "r"(b0), "r"(b1));
}

__global__ void __launch_bounds__(256, 2) mma_gemm_kernel(
    const uint32_t* __restrict__ Agh, const uint32_t* __restrict__ Agl, int K2,
    const uint32_t* __restrict__ Wlh, const uint32_t* __restrict__ Wll,
    const uint32_t* __restrict__ Wrh, const uint32_t* __restrict__ Wrl,
    const float* __restrict__ bias,
    uint32_t* __restrict__ Cq, float* __restrict__ Cr, int Nn)
{
    extern __shared__ uint32_t smu[];
    uint32_t sbase = smem_u32(smu);

    const uint32_t* Wgh = (blockIdx.y == 0) ? Wlh : Wrh;
    const uint32_t* Wgl = (blockIdx.y == 0) ? Wll : Wrl;
    const bool isRoot = (blockIdx.y == 1);

    int tid = threadIdx.x, lane = tid & 31, wid = tid >> 5;
    int wm = wid >> 1, wn = wid & 1;
    int row0 = blockIdx.x * 128;

    float acc[2][8][4];
#pragma unroll
    for (int mt = 0; mt < 2; mt++)
#pragma unroll
        for (int nt = 0; nt < 8; nt++)
#pragma unroll
            for (int j = 0; j < 4; j++) acc[mt][nt][j] = 0.0f;

    int rq = lane >> 2, cq = lane & 3;
    const int NC = K2 >> 4;   // chunks of 16 k-pairs (BK=32)

    auto loadStage = [&](int i) {
        int st = i & 1;
        int kc2 = i << 4;
        uint32_t sa = sbase + (uint32_t)(st * STAGE_U) * 4;
        uint32_t sw = sa + (uint32_t)(2 * A_U) * 4;
#pragma unroll
        for (int it = 0; it < 2; it++) {
            int lin = tid + it * 256;
            int r = lin >> 2, c = (lin & 3) * 4;
            int gr = row0 + r;
            const uint32_t* sh = Agh + (size_t)gr * K2 + kc2 + c;
            const uint32_t* sl = Agl + (size_t)gr * K2 + kc2 + c;
            cpa16(sa + (uint32_t)(r * A_LDp + c) * 4, sh, gr < Nn);
            cpa16(sa + (uint32_t)(A_U + r * A_LDp + c) * 4, sl, gr < Nn);
        }
#pragma unroll
        for (int it = 0; it < 2; it++) {
            int lin = tid + it * 256;
            int r = lin >> 5, c = (lin & 31) * 4;
            cpa16(sw + (uint32_t)(r * W_LDp + c) * 4, Wgh + (size_t)(kc2 + r) * 128 + c, true);
            cpa16(sw + (uint32_t)(W_U + r * W_LDp + c) * 4, Wgl + (size_t)(kc2 + r) * 128 + c, true);
        }
    };

    loadStage(0);
    cpa_commit();

    for (int i = 0; i < NC; i++) {
        if (i + 1 < NC) {
            loadStage(i + 1);
            cpa_commit();
            cpa_wait<1>();
        } else {
            cpa_wait<0>();
        }
        __syncthreads();

        const uint32_t* S = smu + (i & 1) * STAGE_U;
        const uint32_t* AHs = S;
        const uint32_t* ALs = S + A_U;
        const uint32_t* WHs = S + 2 * A_U;
        const uint32_t* WLs = WHs + W_U;

#pragma unroll
        for (int ks = 0; ks < 2; ks++) {
            int kb2 = ks * 8;
            uint32_t ah[2][4], al[2][4];
#pragma unroll
            for (int mt = 0; mt < 2; mt++) {
                int m0 = wm * 32 + mt * 16 + rq;
                int i00 = m0 * A_LDp + kb2 + cq;
                int i10 = (m0 + 8) * A_LDp + kb2 + cq;
                ah[mt][0] = AHs[i00];     al[mt][0] = ALs[i00];
                ah[mt][1] = AHs[i10];     al[mt][1] = ALs[i10];
                ah[mt][2] = AHs[i00 + 4]; al[mt][2] = ALs[i00 + 4];
                ah[mt][3] = AHs[i10 + 4]; al[mt][3] = ALs[i10 + 4];
            }
#pragma unroll
            for (int nt = 0; nt < 8; nt++) {
                int n0 = wn * 64 + nt * 8 + rq;
                int k0 = (kb2 + cq) * W_LDp + n0;
                int k1 = (kb2 + cq + 4) * W_LDp + n0;
                uint32_t bh0 = WHs[k0], bh1 = WHs[k1];
                uint32_t bl0 = WLs[k0], bl1 = WLs[k1];
#pragma unroll
                for (int mt = 0; mt < 2; mt++) {
                    mma_bf16(acc[mt][nt], ah[mt], bh0, bh1);
                    mma_bf16(acc[mt][nt], ah[mt], bl0, bl1);
                    mma_bf16(acc[mt][nt], al[mt], bh0, bh1);
                }
            }
        }
        __syncthreads();
    }

    // epilogue
    int c2 = (lane & 3) * 2;
#pragma unroll
    for (int mt = 0; mt < 2; mt++) {
#pragma unroll
        for (int nt = 0; nt < 8; nt++) {
            int gc = wn * 64 + nt * 8 + c2;
            int gr0 = row0 + wm * 32 + mt * 16 + rq;
            int gr1 = gr0 + 8;
            if (isRoot) {
                float bv0 = bias[gc], bv1 = bias[gc + 1];
                if (gr0 < Nn) {
                    float2 v = make_float2(acc[mt][nt][0] + bv0, acc[mt][nt][1] + bv1);
                    *(float2*)&Cr[(size_t)gr0 * 128 + gc] = v;
                }
                if (gr1 < Nn) {
                    float2 v = make_float2(acc[mt][nt][2] + bv0, acc[mt][nt][3] + bv1);
                    *(float2*)&Cr[(size_t)gr1 * 128 + gc] = v;
                }
            } else {
                if (gr0 < Nn) {
                    __half2 hv = __floats2half2_rn(acc[mt][nt][0], acc[mt][nt][1]);
                    Cq[(size_t)gr0 * 64 + (gc >> 1)] = *(uint32_t*)&hv;
                }
                if (gr1 < Nn) {
                    __half2 hv = __floats2half2_rn(acc[mt][nt][2], acc[mt][nt][3]);
                    Cq[(size_t)gr1 * 64 + (gc >> 1)] = *(uint32_t*)&hv;
                }
            }
        }
    }
}

// ---------------- CSR mean-aggregation: one warp per node ----------------
// Gathers half2-packed Cq rows (256 B/row), accumulates fp32.
// Also emits packed bf16-split of relu(h) for the next layer's GEMM.
__global__ void agg_kernel(const uint32_t* __restrict__ Cq, const float* __restrict__ Cr,
                           const int* __restrict__ rowptr, const int* __restrict__ colA,
                           float* __restrict__ Hout,
                           uint32_t* __restrict__ Ahh, uint32_t* __restrict__ Ahl, int Nn) {
    int warp = (blockIdx.x * blockDim.x + threadIdx.x) >> 5;
    int lane = threadIdx.x & 31;
    if (warp >= Nn) return;
    int beg = rowptr[warp], end = rowptr[warp + 1];
    float4 acc0 = make_float4(0.f, 0.f, 0.f, 0.f);
    float4 acc1 = make_float4(0.f, 0.f, 0.f, 0.f);
    int j = beg;
    for (; j + 1 < end; j += 2) {
        int s0 = colA[j], s1 = colA[j + 1];
        uint2 u0 = *(const uint2*)&Cq[(size_t)s0 * 64 + lane * 2];
        uint2 u1 = *(const uint2*)&Cq[(size_t)s1 * 64 + lane * 2];
        float2 a0 = __half22float2(*(__half2*)&u0.x);
        float2 b0 = __half22float2(*(__half2*)&u0.y);
        float2 a1 = __half22float2(*(__half2*)&u1.x);
        float2 b1 = __half22float2(*(__half2*)&u1.y);
        acc0.x += a0.x; acc0.y += a0.y; acc0.z += b0.x; acc0.w += b0.y;
        acc1.x += a1.x; acc1.y += a1.y; acc1.z += b1.x; acc1.w += b1.y;
    }
    if (j < end) {
        int s = colA[j];
        uint2 u = *(const uint2*)&Cq[(size_t)s * 64 + lane * 2];
        float2 a = __half22float2(*(__half2*)&u.x);
        float2 b = __half22float2(*(__half2*)&u.y);
        acc0.x += a.x; acc0.y += a.y; acc0.z += b.x; acc0.w += b.y;
    }
    float inv = 1.0f / fmaxf((float)(end - beg), 1.0f);
    float4 r = *(const float4*)&Cr[(size_t)warp * 128 + lane * 4];
    float4 o;
    o.x = (acc0.x + acc1.x) * inv + r.x;
    o.y = (acc0.y + acc1.y) * inv + r.y;
    o.z = (acc0.z + acc1.z) * inv + r.z;
    o.w = (acc0.w + acc1.w) * inv + r.w;
    *(float4*)&Hout[(size_t)warp * 128 + lane * 4] = o;
    // relu + split for next GEMM
    float r0 = fmaxf(o.x, 0.f), r1 = fmaxf(o.y, 0.f);
    float r2 = fmaxf(o.z, 0.f), r3v = fmaxf(o.w, 0.f);
    uint32_t h0, l0, h1, l1;
    split2(r0, r1, h0, l0);
    split2(r2, r3v, h1, l1);
    size_t pb = (size_t)warp * 64 + lane * 2;
    *(uint2*)&Ahh[pb] = make_uint2(h0, h1);
    *(uint2*)&Ahl[pb] = make_uint2(l0, l1);
}

// ---------------- layer 3 ----------------
__global__ void l3_dot_kernel(const float* __restrict__ H, const float* __restrict__ Wl3,
                              const float* __restrict__ Wr3, const float* __restrict__ b3,
                              float* __restrict__ p, float* __restrict__ r3, int Nn) {
    int warp = (blockIdx.x * blockDim.x + threadIdx.x) >> 5;
    int lane = threadIdx.x & 31;
    if (warp >= Nn) return;
    float4 h = *(const float4*)&H[(size_t)warp * 128 + lane * 4];
    h.x = fmaxf(h.x, 0.f); h.y = fmaxf(h.y, 0.f);
    h.z = fmaxf(h.z, 0.f); h.w = fmaxf(h.w, 0.f);
    float4 wl = *(const float4*)&Wl3[lane * 4];
    float4 wr = *(const float4*)&Wr3[lane * 4];
    float sl = h.x * wl.x + h.y * wl.y + h.z * wl.z + h.w * wl.w;
    float sr = h.x * wr.x + h.y * wr.y + h.z * wr.z + h.w * wr.w;
#pragma unroll
    for (int off = 16; off; off >>= 1) {
        sl += __shfl_down_sync(0xffffffffu, sl, off);
        sr += __shfl_down_sync(0xffffffffu, sr, off);
    }
    if (lane == 0) { p[warp] = sl; r3[warp] = sr + b3[0]; }
}

__global__ void l3_agg_kernel(const float* __restrict__ p, const float* __restrict__ r3,
                              const int* __restrict__ rowptr, const int* __restrict__ colA,
                              float* __restrict__ out, float* __restrict__ gsum, int Nn) {
    int warp = (blockIdx.x * blockDim.x + threadIdx.x) >> 5;
    int lane = threadIdx.x & 31;
    int wInBlk = threadIdx.x >> 5;
    float val = 0.f;
    if (warp < Nn) {
        int beg = rowptr[warp], end = rowptr[warp + 1];
        float s = 0.f;
        for (int j = beg + lane; j < end; j += 32) s += p[colA[j]];
#pragma unroll
        for (int off = 16; off; off >>= 1) s += __shfl_down_sync(0xffffffffu, s, off);
        if (lane == 0) {
            float z = s / fmaxf((float)(end - beg), 1.0f) + r3[warp];
            val = 1.0f / (1.0f + expf(-z));
            out[warp] = val;
        }
    }
    __shared__ float sh[8];
    if (lane == 0) sh[wInBlk] = val;
    __syncthreads();
    if (threadIdx.x < 8) {
        float v = sh[threadIdx.x];
#pragma unroll
        for (int off = 4; off; off >>= 1) v += __shfl_down_sync(0x000000ffu, v, off);
        if (threadIdx.x == 0) atomicAdd(gsum, v);
    }
}

__global__ void finalize_kernel(float* __restrict__ out, const float* __restrict__ gsum,
                                int Nn, int out_size) {
    if (out_size > Nn) out[out_size - 1] = gsum[0] / (float)Nn;
}

// ---------------- launch ----------------
extern "C" void kernel_launch(void* const* d_in, const int* in_sizes, int n_in,
                              void* d_out, int out_size) {
    const float* x    = (const float*)d_in[0];
    const float* diff = (const float*)d_in[1];
    const float* rec  = (const float*)d_in[2];
    const float* hid  = (const float*)d_in[3];
    const int*   ei   = (const int*)d_in[4];
    const float* Wl0 = (const float*)d_in[5];
    const float* Wr0 = (const float*)d_in[6];
    const float* b0  = (const float*)d_in[7];
    const float* Wl1 = (const float*)d_in[8];
    const float* Wr1 = (const float*)d_in[9];
    const float* b1  = (const float*)d_in[10];
    const float* Wl2 = (const float*)d_in[11];
    const float* Wr2 = (const float*)d_in[12];
    const float* b2  = (const float*)d_in[13];
    const float* Wl3 = (const float*)d_in[14];
    const float* Wr3 = (const float*)d_in[15];
    const float* b3  = (const float*)d_in[16];
    float* out = (float*)d_out;

    int Nn = in_sizes[0] / 64;
    int E  = in_sizes[4] / 2;

    float *Cr, *h, *p, *r3, *gsum;
    uint32_t *A0h, *A0l, *Ahh, *Ahl, *Cq, *W0, *W1, *W2;
    int *rowptr, *colA, *cnt, *fill, *bsum, *bscan;
    cudaGetSymbolAddress((void**)&A0h, g_A0h);
    cudaGetSymbolAddress((void**)&A0l, g_A0l);
    cudaGetSymbolAddress((void**)&Ahh, g_Ahh);
    cudaGetSymbolAddress((void**)&Ahl, g_Ahl);
    cudaGetSymbolAddress((void**)&Cq, g_Cq);
    cudaGetSymbolAddress((void**)&Cr, g_Cr);
    cudaGetSymbolAddress((void**)&h, g_h);
    cudaGetSymbolAddress((void**)&rowptr, g_rowptr);
    cudaGetSymbolAddress((void**)&colA, g_col);
    cudaGetSymbolAddress((void**)&cnt, g_cnt);
    cudaGetSymbolAddress((void**)&fill, g_fill);
    cudaGetSymbolAddress((void**)&bsum, g_bsum);
    cudaGetSymbolAddress((void**)&bscan, g_bscan);
    cudaGetSymbolAddress((void**)&p, g_p);
    cudaGetSymbolAddress((void**)&r3, g_r3);
    cudaGetSymbolAddress((void**)&gsum, g_sum);
    cudaGetSymbolAddress((void**)&W0, g_W0);
    cudaGetSymbolAddress((void**)&W1, g_W1);
    cudaGetSymbolAddress((void**)&W2, g_W2);

    cudaFuncSetAttribute(mma_gemm_kernel, cudaFuncAttributeMaxDynamicSharedMemorySize, GSMEM);

    int threads = 256;
    int NB = (Nn + 1023) / 1024;
    const int P0 = 128 * 128;   // uint32 per L0 weight matrix half
    const int P1 = 64 * 128;
    int grX = (Nn + 127) / 128;
    int aggBlocks = (Nn + 7) / 8;

    // Launch order: 4th launch (ncu-profiled) is the L0 GEMM.
    concat_kernel<<<(Nn * 128 + threads - 1) / threads, threads>>>(x, diff, rec, hid, A0h, A0l, Nn);  // 1
    prep_w_kernel<<<(P0 + 255) / 256, 256>>>(Wl0, W0 + 0 * P0, W0 + 1 * P0, 128);                     // 2
    prep_w_kernel<<<(P0 + 255) / 256, 256>>>(Wr0, W0 + 2 * P0, W0 + 3 * P0, 128);                     // 3
    mma_gemm_kernel<<<dim3(grX, 2), 256, GSMEM>>>(A0h, A0l, 128, W0 + 0 * P0, W0 + 1 * P0,
                                                  W0 + 2 * P0, W0 + 3 * P0, b0, Cq, Cr, Nn);           // 4 <- profiled
    // CSR build
    zero_kernel<<<256, threads>>>(cnt, fill, gsum, Nn);
    count_kernel<<<(E + threads - 1) / threads, threads>>>(ei, E, cnt);
    scan1_kernel<<<NB, 1024>>>(cnt, rowptr, bsum, Nn);
    scan2_kernel<<<1, 128>>>(bsum, bscan, NB);
    scan3_kernel<<<(Nn + threads - 1) / threads, threads>>>(rowptr, bscan, Nn, E);
    fill_kernel<<<(E + threads - 1) / threads, threads>>>(ei, E, rowptr, fill, colA);
    // remaining weight prep
    prep_w_kernel<<<(P1 + 255) / 256, 256>>>(Wl1, W1 + 0 * P1, W1 + 1 * P1, 64);
    prep_w_kernel<<<(P1 + 255) / 256, 256>>>(Wr1, W1 + 2 * P1, W1 + 3 * P1, 64);
    prep_w_kernel<<<(P1 + 255) / 256, 256>>>(Wl2, W2 + 0 * P1, W2 + 1 * P1, 64);
    prep_w_kernel<<<(P1 + 255) / 256, 256>>>(Wr2, W2 + 2 * P1, W2 + 3 * P1, 64);

    agg_kernel<<<aggBlocks, 256>>>(Cq, Cr, rowptr, colA, h, Ahh, Ahl, Nn);

    mma_gemm_kernel<<<dim3(grX, 2), 256, GSMEM>>>(Ahh, Ahl, 64, W1 + 0 * P1, W1 + 1 * P1,
                                                  W1 + 2 * P1, W1 + 3 * P1, b1, Cq, Cr, Nn);
    agg_kernel<<<aggBlocks, 256>>>(Cq, Cr, rowptr, colA, h, Ahh, Ahl, Nn);

    mma_gemm_kernel<<<dim3(grX, 2), 256, GSMEM>>>(Ahh, Ahl, 64, W2 + 0 * P1, W2 + 1 * P1,
                                                  W2 + 2 * P1, W2 + 3 * P1, b2, Cq, Cr, Nn);
    agg_kernel<<<aggBlocks, 256>>>(Cq, Cr, rowptr, colA, h, Ahh, Ahl, Nn);

    l3_dot_kernel<<<aggBlocks, 256>>>(h, Wl3, Wr3, b3, p, r3, Nn);
    l3_agg_kernel<<<aggBlocks, 256>>>(p, r3, rowptr, colA, out, gsum, Nn);
    finalize_kernel<<<1, 1>>>(out, gsum, Nn, out_size);
}

// round 15
// speedup vs baseline: 1.4348x; 1.4348x over previous
#include <cuda_runtime.h>
#include <cuda_bf16.h>
#include <cuda_fp16.h>
#include <cstdint>
#include <math.h>

// Problem constants
#define MAXN 100000
#define MAXE 1600000
#define NB_MAX ((MAXN + 1023) / 1024)

// ---------------- device scratch ----------------
// packed bf16x2 split inputs (low 16 bits = even k, high = odd k)
__device__ uint32_t g_A0h[MAXN * 128];  // layer0 input hi  (K=256 -> 128 pairs)
__device__ uint32_t g_A0l[MAXN * 128];  // layer0 input lo
__device__ uint32_t g_Ahh[MAXN * 64];   // relu(h) hi (K=128 -> 64 pairs)
__device__ uint32_t g_Ahl[MAXN * 64];   // relu(h) lo
__device__ uint32_t g_Cq[MAXN * 64];    // h@Wl as packed half2 (aggregation gather source)
__device__ float g_Cr[MAXN * 128];      // h@Wr + b (fp32)
__device__ float g_h[MAXN * 128];       // layer output (pre-activation, fp32 for l3)
__device__ int   g_rowptr[MAXN + 1];
__device__ int   g_col[MAXE];
__device__ int   g_cnt[MAXN];
__device__ int   g_fill[MAXN];
__device__ int   g_bsum[NB_MAX + 2];
__device__ int   g_bscan[NB_MAX + 2];
__device__ float g_p[MAXN];
__device__ float g_r3[MAXN];
__device__ float g_sum[1];
// packed bf16-split weights, n-major [n=128][kp]: per layer: l-hi, l-lo, r-hi, r-lo
__device__ uint32_t g_W0[4 * 128 * 128];
__device__ uint32_t g_W1[4 * 128 * 64];
__device__ uint32_t g_W2[4 * 128 * 64];

// ---------------- helpers ----------------
__device__ __forceinline__ uint32_t smem_u32(const void* p) {
    uint32_t a;
    asm("{ .reg .u64 t; cvta.to.shared.u64 t, %1; cvt.u32.u64 %0, t; }" : "=r"(a) : "l"(p));
    return a;
}
__device__ __forceinline__ void cpa16(uint32_t dst, const void* src, bool pred) {
    int sz = pred ? 16 : 0;
    asm volatile("cp.async.cg.shared.global [%0], [%1], 16, %2;" :: "r"(dst), "l"(src), "r"(sz));
}
__device__ __forceinline__ void cpa_commit() { asm volatile("cp.async.commit_group;"); }
template <int NLeft> __device__ __forceinline__ void cpa_wait() {
    asm volatile("cp.async.wait_group %0;" :: "n"(NLeft));
}
__device__ __forceinline__ void ldsm_x4(uint32_t& r0, uint32_t& r1, uint32_t& r2, uint32_t& r3,
                                        uint32_t addr) {
    asm volatile("ldmatrix.sync.aligned.m8n8.x4.shared.b16 {%0,%1,%2,%3}, [%4];"
                 : "=r"(r0), "=r"(r1), "=r"(r2), "=r"(r3) : "r"(addr));
}
// split two fp32 into packed bf16x2 hi/lo
__device__ __forceinline__ void split2(float a, float b, uint32_t& hi, uint32_t& lo) {
    __nv_bfloat16 ha = __float2bfloat16(a);
    __nv_bfloat16 hb = __float2bfloat16(b);
    float ra = a - __bfloat162float(ha);
    float rb = b - __bfloat162float(hb);
    __nv_bfloat16 la = __float2bfloat16(ra);
    __nv_bfloat16 lb = __float2bfloat16(rb);
    hi = ((uint32_t)__bfloat16_as_ushort(hb) << 16) | __bfloat16_as_ushort(ha);
    lo = ((uint32_t)__bfloat16_as_ushort(lb) << 16) | __bfloat16_as_ushort(la);
}

// ---------------- utility kernels ----------------
__global__ void zero_kernel(int* cnt, int* fill, float* gsum, int Nn) {
    int i = blockIdx.x * blockDim.x + threadIdx.x;
    if (i == 0) *gsum = 0.0f;
    for (; i < Nn; i += gridDim.x * blockDim.x) { cnt[i] = 0; fill[i] = 0; }
}

// concat + bf16-split directly into packed layer0 input
__global__ void concat_kernel(const float* __restrict__ x, const float* __restrict__ d,
                              const float* __restrict__ r, const float* __restrict__ hp,
                              uint32_t* __restrict__ A0h, uint32_t* __restrict__ A0l, int Nn) {
    int idx = blockIdx.x * blockDim.x + threadIdx.x;   // one k-pair per thread
    if (idx < Nn * 128) {
        int n = idx >> 7, kp = idx & 127;
        int seg = kp >> 5, w = kp & 31;
        const float* src = (seg == 0) ? x : (seg == 1) ? d : (seg == 2) ? r : hp;
        float2 v = *(const float2*)&src[(size_t)n * 64 + w * 2];
        uint32_t hi, lo;
        split2(v.x, v.y, hi, lo);
        A0h[idx] = hi;
        A0l[idx] = lo;
    }
}

__global__ void count_kernel(const int* __restrict__ ei, int E, int* __restrict__ cnt) {
    int e = blockIdx.x * blockDim.x + threadIdx.x;
    if (e < E) atomicAdd(&cnt[ei[E + e]], 1);
}

__global__ void scan1_kernel(const int* __restrict__ cnt, int* __restrict__ rowptr,
                             int* __restrict__ bsum, int Nn) {
    __shared__ int ws[32];
    int i = blockIdx.x * 1024 + threadIdx.x;
    int lane = threadIdx.x & 31, wid = threadIdx.x >> 5;
    int v = (i < Nn) ? cnt[i] : 0;
    int x = v;
#pragma unroll
    for (int off = 1; off < 32; off <<= 1) {
        int t = __shfl_up_sync(0xffffffffu, x, off);
        if (lane >= off) x += t;
    }
    if (lane == 31) ws[wid] = x;
    __syncthreads();
    if (wid == 0) {
        int w = ws[lane];
#pragma unroll
        for (int off = 1; off < 32; off <<= 1) {
            int t = __shfl_up_sync(0xffffffffu, w, off);
            if (lane >= off) w += t;
        }
        ws[lane] = w;
    }
    __syncthreads();
    int base = (wid > 0) ? ws[wid - 1] : 0;
    if (i < Nn) rowptr[i] = base + x - v;
    if (threadIdx.x == 1023) bsum[blockIdx.x] = base + x;
}

__global__ void scan2_kernel(const int* __restrict__ bsum, int* __restrict__ bscan, int NB) {
    __shared__ int ws[4];
    int tid = threadIdx.x, lane = tid & 31, wid = tid >> 5;
    int v = (tid < NB) ? bsum[tid] : 0;
    int x = v;
#pragma unroll
    for (int off = 1; off < 32; off <<= 1) {
        int t = __shfl_up_sync(0xffffffffu, x, off);
        if (lane >= off) x += t;
    }
    if (lane == 31) ws[wid] = x;
    __syncthreads();
    int base = 0;
    for (int t = 0; t < wid; t++) base += ws[t];
    if (tid < NB) bscan[tid] = base + x - v;
}

__global__ void scan3_kernel(int* __restrict__ rowptr, const int* __restrict__ bscan,
                             int Nn, int E) {
    int i = blockIdx.x * blockDim.x + threadIdx.x;
    if (i < Nn) rowptr[i] += bscan[i >> 10];
    if (i == 0) rowptr[Nn] = E;
}

__global__ void fill_kernel(const int* __restrict__ ei, int E,
                            const int* __restrict__ rowptr, int* __restrict__ fill,
                            int* __restrict__ colA) {
    int e = blockIdx.x * blockDim.x + threadIdx.x;
    if (e < E) {
        int src = ei[e];
        int dst = ei[E + e];
        int pos = atomicAdd(&fill[dst], 1);
        colA[rowptr[dst] + pos] = src;
    }
}

// weight prep: bf16 split + pack pairs along k; output n-major [n][K2]
__global__ void prep_w_kernel(const float* __restrict__ W, uint32_t* __restrict__ Hi,
                              uint32_t* __restrict__ Lo, int K2) {
    int idx = blockIdx.x * blockDim.x + threadIdx.x;
    if (idx < K2 * 128) {
        int n = idx / K2, kp = idx - n * K2;
        float v0 = W[(size_t)(2 * kp) * 128 + n];
        float v1 = W[(size_t)(2 * kp + 1) * 128 + n];
        uint32_t hi, lo;
        split2(v0, v1, hi, lo);
        Hi[idx] = hi;
        Lo[idx] = lo;
    }
}

// ---------------- bf16x3 split mma.sync GEMM, cp.async + ldmatrix ----------------
// grid (ceil(N/128), 2): y=0 -> Cq (half2) = A@Wl ; y=1 -> Cr (fp32) = A@Wr + b
// BM=128, BN=128, BK=32 (16 k-pairs); 8 warps 4(m)x2(n); warp tile 32x64; m16n8k16 x3.
// SMEM per stage (uint32): A hi/lo [128][20], W hi/lo [128][20] (n-major).
#define LDP    20                     // padded stride (conflict-free for ldmatrix row groups)
#define A_U    (128 * LDP)            // 2560
#define W_U    (128 * LDP)            // 2560
#define STAGE_U (2 * A_U + 2 * W_U)   // 10240 uint32 = 40960 B
#define GSMEM  (2 * STAGE_U * 4)      // 81920 bytes

__device__ __forceinline__ void mma_bf16(float* d, const uint32_t* a, uint32_t b0, uint32_t b1) {
    asm volatile(
        "mma.sync.aligned.m16n8k16.row.col.f32.bf16.bf16.f32 "
        "{%0,%1,%2,%3}, {%4,%5,%6,%7}, {%8,%9}, {%0,%1,%2,%3};"
        : "+f"(d[0]), "+f"(d[1]), "+f"(d[2]), "+f"(d[3])
        : "r"(a[0]), "r"(a[1]), "r"(a[2]), "r"(a[3]), "r"(b0), "r"(b1));
}

__global__ void __launch_bounds__(256, 2) mma_gemm_kernel(
    const uint32_t* __restrict__ Agh, const uint32_t* __restrict__ Agl, int K2,
    const uint32_t* __restrict__ Wlh, const uint32_t* __restrict__ Wll,
    const uint32_t* __restrict__ Wrh, const uint32_t* __restrict__ Wrl,
    const float* __restrict__ bias,
    uint32_t* __restrict__ Cq, float* __restrict__ Cr, int Nn)
{
    extern __shared__ uint32_t smu[];
    uint32_t sbase = smem_u32(smu);

    const uint32_t* Wgh = (blockIdx.y == 0) ? Wlh : Wrh;
    const uint32_t* Wgl = (blockIdx.y == 0) ? Wll : Wrl;
    const bool isRoot = (blockIdx.y == 1);

    int tid = threadIdx.x, lane = tid & 31, wid = tid >> 5;
    int wm = wid >> 1, wn = wid & 1;
    int row0 = blockIdx.x * 128;

    float acc[2][8][4];
#pragma unroll
    for (int mt = 0; mt < 2; mt++)
#pragma unroll
        for (int nt = 0; nt < 8; nt++)
#pragma unroll
            for (int j = 0; j < 4; j++) acc[mt][nt][j] = 0.0f;

    int rq = lane >> 2, cq = lane & 3;
    const int NC = K2 >> 4;   // chunks of 16 k-pairs (BK=32)

    // per-lane ldmatrix address components (uint32-offset units)
    int aRow = wm * 32 + (lane & 15);            // + mt*16
    int aCol = (lane >> 4) * 4;                  // + kb2
    int wRow = wn * 64 + (lane & 7) + ((lane >> 4) & 1) * 8;  // + ntp*16
    int wCol = ((lane >> 3) & 1) * 4;            // + kb2

    auto loadStage = [&](int i) {
        int st = i & 1;
        int kc2 = i << 4;
        uint32_t sa = sbase + (uint32_t)(st * STAGE_U) * 4;
        uint32_t sw = sa + (uint32_t)(2 * A_U) * 4;
#pragma unroll
        for (int it = 0; it < 2; it++) {
            int lin = tid + it * 256;
            int r = lin >> 2, c = (lin & 3) * 4;
            int gr = row0 + r;
            cpa16(sa + (uint32_t)(r * LDP + c) * 4, Agh + (size_t)gr * K2 + kc2 + c, gr < Nn);
            cpa16(sa + (uint32_t)(A_U + r * LDP + c) * 4, Agl + (size_t)gr * K2 + kc2 + c, gr < Nn);
        }
#pragma unroll
        for (int it = 0; it < 2; it++) {
            int lin = tid + it * 256;
            int n = lin >> 2, c = (lin & 3) * 4;
            cpa16(sw + (uint32_t)(n * LDP + c) * 4, Wgh + (size_t)n * K2 + kc2 + c, true);
            cpa16(sw + (uint32_t)(W_U + n * LDP + c) * 4, Wgl + (size_t)n * K2 + kc2 + c, true);
        }
    };

    loadStage(0);
    cpa_commit();

    for (int i = 0; i < NC; i++) {
        if (i + 1 < NC) {
            loadStage(i + 1);
            cpa_commit();
            cpa_wait<1>();
        } else {
            cpa_wait<0>();
        }
        __syncthreads();

        uint32_t sa = sbase + (uint32_t)((i & 1) * STAGE_U) * 4;
        uint32_t sw = sa + (uint32_t)(2 * A_U) * 4;

#pragma unroll
        for (int ks = 0; ks < 2; ks++) {
            int kb2 = ks * 8;
            uint32_t ah[2][4], al[2][4];
#pragma unroll
            for (int mt = 0; mt < 2; mt++) {
                uint32_t aaddr = sa + (uint32_t)(((aRow + mt * 16) * LDP) + kb2 + aCol) * 4;
                ldsm_x4(ah[mt][0], ah[mt][1], ah[mt][2], ah[mt][3], aaddr);
                ldsm_x4(al[mt][0], al[mt][1], al[mt][2], al[mt][3], aaddr + A_U * 4);
            }
            uint32_t bh[8][2], bl[8][2];
#pragma unroll
            for (int ntp = 0; ntp < 4; ntp++) {
                uint32_t waddr = sw + (uint32_t)(((wRow + ntp * 16) * LDP) + kb2 + wCol) * 4;
                ldsm_x4(bh[2 * ntp][0], bh[2 * ntp][1], bh[2 * ntp + 1][0], bh[2 * ntp + 1][1], waddr);
                ldsm_x4(bl[2 * ntp][0], bl[2 * ntp][1], bl[2 * ntp + 1][0], bl[2 * ntp + 1][1],
                        waddr + W_U * 4);
            }
#pragma unroll
            for (int nt = 0; nt < 8; nt++) {
#pragma unroll
                for (int mt = 0; mt < 2; mt++) {
                    mma_bf16(acc[mt][nt], ah[mt], bh[nt][0], bh[nt][1]);
                    mma_bf16(acc[mt][nt], ah[mt], bl[nt][0], bl[nt][1]);
                    mma_bf16(acc[mt][nt], al[mt], bh[nt][0], bh[nt][1]);
                }
            }
        }
        __syncthreads();
    }

    // epilogue
    int c2 = (lane & 3) * 2;
#pragma unroll
    for (int mt = 0; mt < 2; mt++) {
#pragma unroll
        for (int nt = 0; nt < 8; nt++) {
            int gc = wn * 64 + nt * 8 + c2;
            int gr0 = row0 + wm * 32 + mt * 16 + rq;
            int gr1 = gr0 + 8;
            if (isRoot) {
                float bv0 = bias[gc], bv1 = bias[gc + 1];
                if (gr0 < Nn) {
                    float2 v = make_float2(acc[mt][nt][0] + bv0, acc[mt][nt][1] + bv1);
                    *(float2*)&Cr[(size_t)gr0 * 128 + gc] = v;
                }
                if (gr1 < Nn) {
                    float2 v = make_float2(acc[mt][nt][2] + bv0, acc[mt][nt][3] + bv1);
                    *(float2*)&Cr[(size_t)gr1 * 128 + gc] = v;
                }
            } else {
                if (gr0 < Nn) {
                    __half2 hv = __floats2half2_rn(acc[mt][nt][0], acc[mt][nt][1]);
                    Cq[(size_t)gr0 * 64 + (gc >> 1)] = *(uint32_t*)&hv;
                }
                if (gr1 < Nn) {
                    __half2 hv = __floats2half2_rn(acc[mt][nt][2], acc[mt][nt][3]);
                    Cq[(size_t)gr1 * 64 + (gc >> 1)] = *(uint32_t*)&hv;
                }
            }
        }
    }
}

// ---------------- CSR mean-aggregation: one warp per node ----------------
// Gathers half2-packed Cq rows (256 B/row), accumulates fp32.
// Also emits packed bf16-split of relu(h) for the next layer's GEMM.
__global__ void agg_kernel(const uint32_t* __restrict__ Cq, const float* __restrict__ Cr,
                           const int* __restrict__ rowptr, const int* __restrict__ colA,
                           float* __restrict__ Hout,
                           uint32_t* __restrict__ Ahh, uint32_t* __restrict__ Ahl, int Nn) {
    int warp = (blockIdx.x * blockDim.x + threadIdx.x) >> 5;
    int lane = threadIdx.x & 31;
    if (warp >= Nn) return;
    int beg = rowptr[warp], end = rowptr[warp + 1];
    float4 acc0 = make_float4(0.f, 0.f, 0.f, 0.f);
    float4 acc1 = make_float4(0.f, 0.f, 0.f, 0.f);
    int j = beg;
    for (; j + 1 < end; j += 2) {
        int s0 = colA[j], s1 = colA[j + 1];
        uint2 u0 = *(const uint2*)&Cq[(size_t)s0 * 64 + lane * 2];
        uint2 u1 = *(const uint2*)&Cq[(size_t)s1 * 64 + lane * 2];
        float2 a0 = __half22float2(*(__half2*)&u0.x);
        float2 b0 = __half22float2(*(__half2*)&u0.y);
        float2 a1 = __half22float2(*(__half2*)&u1.x);
        float2 b1 = __half22float2(*(__half2*)&u1.y);
        acc0.x += a0.x; acc0.y += a0.y; acc0.z += b0.x; acc0.w += b0.y;
        acc1.x += a1.x; acc1.y += a1.y; acc1.z += b1.x; acc1.w += b1.y;
    }
    if (j < end) {
        int s = colA[j];
        uint2 u = *(const uint2*)&Cq[(size_t)s * 64 + lane * 2];
        float2 a = __half22float2(*(__half2*)&u.x);
        float2 b = __half22float2(*(__half2*)&u.y);
        acc0.x += a.x; acc0.y += a.y; acc0.z += b.x; acc0.w += b.y;
    }
    float inv = 1.0f / fmaxf((float)(end - beg), 1.0f);
    float4 r = *(const float4*)&Cr[(size_t)warp * 128 + lane * 4];
    float4 o;
    o.x = (acc0.x + acc1.x) * inv + r.x;
    o.y = (acc0.y + acc1.y) * inv + r.y;
    o.z = (acc0.z + acc1.z) * inv + r.z;
    o.w = (acc0.w + acc1.w) * inv + r.w;
    *(float4*)&Hout[(size_t)warp * 128 + lane * 4] = o;
    // relu + split for next GEMM
    float r0 = fmaxf(o.x, 0.f), r1 = fmaxf(o.y, 0.f);
    float r2 = fmaxf(o.z, 0.f), r3v = fmaxf(o.w, 0.f);
    uint32_t h0, l0, h1, l1;
    split2(r0, r1, h0, l0);
    split2(r2, r3v, h1, l1);
    size_t pb = (size_t)warp * 64 + lane * 2;
    *(uint2*)&Ahh[pb] = make_uint2(h0, h1);
    *(uint2*)&Ahl[pb] = make_uint2(l0, l1);
}

// ---------------- layer 3 ----------------
__global__ void l3_dot_kernel(const float* __restrict__ H, const float* __restrict__ Wl3,
                              const float* __restrict__ Wr3, const float* __restrict__ b3,
                              float* __restrict__ p, float* __restrict__ r3, int Nn) {
    int warp = (blockIdx.x * blockDim.x + threadIdx.x) >> 5;
    int lane = threadIdx.x & 31;
    if (warp >= Nn) return;
    float4 h = *(const float4*)&H[(size_t)warp * 128 + lane * 4];
    h.x = fmaxf(h.x, 0.f); h.y = fmaxf(h.y, 0.f);
    h.z = fmaxf(h.z, 0.f); h.w = fmaxf(h.w, 0.f);
    float4 wl = *(const float4*)&Wl3[lane * 4];
    float4 wr = *(const float4*)&Wr3[lane * 4];
    float sl = h.x * wl.x + h.y * wl.y + h.z * wl.z + h.w * wl.w;
    float sr = h.x * wr.x + h.y * wr.y + h.z * wr.z + h.w * wr.w;
#pragma unroll
    for (int off = 16; off; off >>= 1) {
        sl += __shfl_down_sync(0xffffffffu, sl, off);
        sr += __shfl_down_sync(0xffffffffu, sr, off);
    }
    if (lane == 0) { p[warp] = sl; r3[warp] = sr + b3[0]; }
}

__global__ void l3_agg_kernel(const float* __restrict__ p, const float* __restrict__ r3,
                              const int* __restrict__ rowptr, const int* __restrict__ colA,
                              float* __restrict__ out, float* __restrict__ gsum, int Nn) {
    int warp = (blockIdx.x * blockDim.x + threadIdx.x) >> 5;
    int lane = threadIdx.x & 31;
    int wInBlk = threadIdx.x >> 5;
    float val = 0.f;
    if (warp < Nn) {
        int beg = rowptr[warp], end = rowptr[warp + 1];
        float s = 0.f;
        for (int j = beg + lane; j < end; j += 32) s += p[colA[j]];
#pragma unroll
        for (int off = 16; off; off >>= 1) s += __shfl_down_sync(0xffffffffu, s, off);
        if (lane == 0) {
            float z = s / fmaxf((float)(end - beg), 1.0f) + r3[warp];
            val = 1.0f / (1.0f + expf(-z));
            out[warp] = val;
        }
    }
    __shared__ float sh[8];
    if (lane == 0) sh[wInBlk] = val;
    __syncthreads();
    if (threadIdx.x < 8) {
        float v = sh[threadIdx.x];
#pragma unroll
        for (int off = 4; off; off >>= 1) v += __shfl_down_sync(0x000000ffu, v, off);
        if (threadIdx.x == 0) atomicAdd(gsum, v);
    }
}

__global__ void finalize_kernel(float* __restrict__ out, const float* __restrict__ gsum,
                                int Nn, int out_size) {
    if (out_size > Nn) out[out_size - 1] = gsum[0] / (float)Nn;
}

// ---------------- launch ----------------
extern "C" void kernel_launch(void* const* d_in, const int* in_sizes, int n_in,
                              void* d_out, int out_size) {
    const float* x    = (const float*)d_in[0];
    const float* diff = (const float*)d_in[1];
    const float* rec  = (const float*)d_in[2];
    const float* hid  = (const float*)d_in[3];
    const int*   ei   = (const int*)d_in[4];
    const float* Wl0 = (const float*)d_in[5];
    const float* Wr0 = (const float*)d_in[6];
    const float* b0  = (const float*)d_in[7];
    const float* Wl1 = (const float*)d_in[8];
    const float* Wr1 = (const float*)d_in[9];
    const float* b1  = (const float*)d_in[10];
    const float* Wl2 = (const float*)d_in[11];
    const float* Wr2 = (const float*)d_in[12];
    const float* b2  = (const float*)d_in[13];
    const float* Wl3 = (const float*)d_in[14];
    const float* Wr3 = (const float*)d_in[15];
    const float* b3  = (const float*)d_in[16];
    float* out = (float*)d_out;

    int Nn = in_sizes[0] / 64;
    int E  = in_sizes[4] / 2;

    float *Cr, *h, *p, *r3, *gsum;
    uint32_t *A0h, *A0l, *Ahh, *Ahl, *Cq, *W0, *W1, *W2;
    int *rowptr, *colA, *cnt, *fill, *bsum, *bscan;
    cudaGetSymbolAddress((void**)&A0h, g_A0h);
    cudaGetSymbolAddress((void**)&A0l, g_A0l);
    cudaGetSymbolAddress((void**)&Ahh, g_Ahh);
    cudaGetSymbolAddress((void**)&Ahl, g_Ahl);
    cudaGetSymbolAddress((void**)&Cq, g_Cq);
    cudaGetSymbolAddress((void**)&Cr, g_Cr);
    cudaGetSymbolAddress((void**)&h, g_h);
    cudaGetSymbolAddress((void**)&rowptr, g_rowptr);
    cudaGetSymbolAddress((void**)&colA, g_col);
    cudaGetSymbolAddress((void**)&cnt, g_cnt);
    cudaGetSymbolAddress((void**)&fill, g_fill);
    cudaGetSymbolAddress((void**)&bsum, g_bsum);
    cudaGetSymbolAddress((void**)&bscan, g_bscan);
    cudaGetSymbolAddress((void**)&p, g_p);
    cudaGetSymbolAddress((void**)&r3, g_r3);
    cudaGetSymbolAddress((void**)&gsum, g_sum);
    cudaGetSymbolAddress((void**)&W0, g_W0);
    cudaGetSymbolAddress((void**)&W1, g_W1);
    cudaGetSymbolAddress((void**)&W2, g_W2);

    cudaFuncSetAttribute(mma_gemm_kernel, cudaFuncAttributeMaxDynamicSharedMemorySize, GSMEM);

    int threads = 256;
    int NB = (Nn + 1023) / 1024;
    const int P0 = 128 * 128;   // uint32 per L0 weight matrix half
    const int P1 = 128 * 64;
    int grX = (Nn + 127) / 128;
    int aggBlocks = (Nn + 7) / 8;

    // Launch order: 4th launch (ncu-profiled) is the L0 GEMM.
    concat_kernel<<<(Nn * 128 + threads - 1) / threads, threads>>>(x, diff, rec, hid, A0h, A0l, Nn);  // 1
    prep_w_kernel<<<(P0 + 255) / 256, 256>>>(Wl0, W0 + 0 * P0, W0 + 1 * P0, 128);                     // 2
    prep_w_kernel<<<(P0 + 255) / 256, 256>>>(Wr0, W0 + 2 * P0, W0 + 3 * P0, 128);                     // 3
    mma_gemm_kernel<<<dim3(grX, 2), 256, GSMEM>>>(A0h, A0l, 128, W0 + 0 * P0, W0 + 1 * P0,
                                                  W0 + 2 * P0, W0 + 3 * P0, b0, Cq, Cr, Nn);           // 4 <- profiled
    // CSR build
    zero_kernel<<<256, threads>>>(cnt, fill, gsum, Nn);
    count_kernel<<<(E + threads - 1) / threads, threads>>>(ei, E, cnt);
    scan1_kernel<<<NB, 1024>>>(cnt, rowptr, bsum, Nn);
    scan2_kernel<<<1, 128>>>(bsum, bscan, NB);
    scan3_kernel<<<(Nn + threads - 1) / threads, threads>>>(rowptr, bscan, Nn, E);
    fill_kernel<<<(E + threads - 1) / threads, threads>>>(ei, E, rowptr, fill, colA);
    // remaining weight prep
    prep_w_kernel<<<(P1 + 255) / 256, 256>>>(Wl1, W1 + 0 * P1, W1 + 1 * P1, 64);
    prep_w_kernel<<<(P1 + 255) / 256, 256>>>(Wr1, W1 + 2 * P1, W1 + 3 * P1, 64);
    prep_w_kernel<<<(P1 + 255) / 256, 256>>>(Wl2, W2 + 0 * P1, W2 + 1 * P1, 64);
    prep_w_kernel<<<(P1 + 255) / 256, 256>>>(Wr2, W2 + 2 * P1, W2 + 3 * P1, 64);

    agg_kernel<<<aggBlocks, 256>>>(Cq, Cr, rowptr, colA, h, Ahh, Ahl, Nn);

    mma_gemm_kernel<<<dim3(grX, 2), 256, GSMEM>>>(Ahh, Ahl, 64, W1 + 0 * P1, W1 + 1 * P1,
                                                  W1 + 2 * P1, W1 + 3 * P1, b1, Cq, Cr, Nn);
    agg_kernel<<<aggBlocks, 256>>>(Cq, Cr, rowptr, colA, h, Ahh, Ahl, Nn);

    mma_gemm_kernel<<<dim3(grX, 2), 256, GSMEM>>>(Ahh, Ahl, 64, W2 + 0 * P1, W2 + 1 * P1,
                                                  W2 + 2 * P1, W2 + 3 * P1, b2, Cq, Cr, Nn);
    agg_kernel<<<aggBlocks, 256>>>(Cq, Cr, rowptr, colA, h, Ahh, Ahl, Nn);

    l3_dot_kernel<<<aggBlocks, 256>>>(h, Wl3, Wr3, b3, p, r3, Nn);
    l3_agg_kernel<<<aggBlocks, 256>>>(p, r3, rowptr, colA, out, gsum, Nn);
    finalize_kernel<<<1, 1>>>(out, gsum, Nn, out_size);
}

// round 16
// speedup vs baseline: 1.4996x; 1.0452x over previous
#include <cuda_runtime.h>
#include <cuda_bf16.h>
#include <cuda_fp16.h>
#include <cstdint>
#include <math.h>

// Problem constants
#define MAXN 100000
#define MAXE 1600000
#define NB_MAX ((MAXN + 1023) / 1024)

// ---------------- device scratch ----------------
// packed bf16x2 split inputs (low 16 bits = even k, high = odd k)
__device__ uint32_t g_A0h[MAXN * 128];  // layer0 input hi  (K=256 -> 128 pairs)
__device__ uint32_t g_A0l[MAXN * 128];  // layer0 input lo
__device__ uint32_t g_Ahh[MAXN * 64];   // relu(h) hi (K=128 -> 64 pairs)
__device__ uint32_t g_Ahl[MAXN * 64];   // relu(h) lo
__device__ uint32_t g_Cq[MAXN * 64];    // h@Wl as packed half2 (aggregation gather source)
__device__ float g_Cr[MAXN * 128];      // h@Wr + b (fp32)
__device__ int   g_rowptr[MAXN + 1];
__device__ int   g_col[MAXE];
__device__ int   g_cnt[MAXN];
__device__ int   g_fill[MAXN];
__device__ int   g_bsum[NB_MAX + 2];
__device__ int   g_bscan[NB_MAX + 2];
__device__ float g_p[MAXN];
__device__ float g_r3[MAXN];
__device__ float g_sum[1];
// packed bf16-split weights, n-major [n=128][kp]: per layer: l-hi, l-lo, r-hi, r-lo
__device__ uint32_t g_W0[4 * 128 * 128];
__device__ uint32_t g_W1[4 * 128 * 64];
__device__ uint32_t g_W2[4 * 128 * 64];

// ---------------- helpers ----------------
__device__ __forceinline__ uint32_t smem_u32(const void* p) {
    uint32_t a;
    asm("{ .reg .u64 t; cvta.to.shared.u64 t, %1; cvt.u32.u64 %0, t; }" : "=r"(a) : "l"(p));
    return a;
}
__device__ __forceinline__ void cpa16(uint32_t dst, const void* src, bool pred) {
    int sz = pred ? 16 : 0;
    asm volatile("cp.async.cg.shared.global [%0], [%1], 16, %2;" :: "r"(dst), "l"(src), "r"(sz));
}
__device__ __forceinline__ void cpa_commit() { asm volatile("cp.async.commit_group;"); }
template <int NLeft> __device__ __forceinline__ void cpa_wait() {
    asm volatile("cp.async.wait_group %0;" :: "n"(NLeft));
}
__device__ __forceinline__ void ldsm_x4(uint32_t& r0, uint32_t& r1, uint32_t& r2, uint32_t& r3,
                                        uint32_t addr) {
    asm volatile("ldmatrix.sync.aligned.m8n8.x4.shared.b16 {%0,%1,%2,%3}, [%4];"
                 : "=r"(r0), "=r"(r1), "=r"(r2), "=r"(r3) : "r"(addr));
}
// split two fp32 into packed bf16x2 hi/lo
__device__ __forceinline__ void split2(float a, float b, uint32_t& hi, uint32_t& lo) {
    __nv_bfloat16 ha = __float2bfloat16(a);
    __nv_bfloat16 hb = __float2bfloat16(b);
    float ra = a - __bfloat162float(ha);
    float rb = b - __bfloat162float(hb);
    __nv_bfloat16 la = __float2bfloat16(ra);
    __nv_bfloat16 lb = __float2bfloat16(rb);
    hi = ((uint32_t)__bfloat16_as_ushort(hb) << 16) | __bfloat16_as_ushort(ha);
    lo = ((uint32_t)__bfloat16_as_ushort(lb) << 16) | __bfloat16_as_ushort(la);
}

// ---------------- utility kernels ----------------
__global__ void zero_kernel(int* cnt, int* fill, float* gsum, int Nn) {
    int i = blockIdx.x * blockDim.x + threadIdx.x;
    if (i == 0) *gsum = 0.0f;
    for (; i < Nn; i += gridDim.x * blockDim.x) { cnt[i] = 0; fill[i] = 0; }
}

// concat + bf16-split directly into packed layer0 input
__global__ void concat_kernel(const float* __restrict__ x, const float* __restrict__ d,
                              const float* __restrict__ r, const float* __restrict__ hp,
                              uint32_t* __restrict__ A0h, uint32_t* __restrict__ A0l, int Nn) {
    int idx = blockIdx.x * blockDim.x + threadIdx.x;   // one k-pair per thread
    if (idx < Nn * 128) {
        int n = idx >> 7, kp = idx & 127;
        int seg = kp >> 5, w = kp & 31;
        const float* src = (seg == 0) ? x : (seg == 1) ? d : (seg == 2) ? r : hp;
        float2 v = *(const float2*)&src[(size_t)n * 64 + w * 2];
        uint32_t hi, lo;
        split2(v.x, v.y, hi, lo);
        A0h[idx] = hi;
        A0l[idx] = lo;
    }
}

__global__ void count_kernel(const int* __restrict__ ei, int E, int* __restrict__ cnt) {
    int e = blockIdx.x * blockDim.x + threadIdx.x;
    if (e < E) atomicAdd(&cnt[ei[E + e]], 1);
}

__global__ void scan1_kernel(const int* __restrict__ cnt, int* __restrict__ rowptr,
                             int* __restrict__ bsum, int Nn) {
    __shared__ int ws[32];
    int i = blockIdx.x * 1024 + threadIdx.x;
    int lane = threadIdx.x & 31, wid = threadIdx.x >> 5;
    int v = (i < Nn) ? cnt[i] : 0;
    int x = v;
#pragma unroll
    for (int off = 1; off < 32; off <<= 1) {
        int t = __shfl_up_sync(0xffffffffu, x, off);
        if (lane >= off) x += t;
    }
    if (lane == 31) ws[wid] = x;
    __syncthreads();
    if (wid == 0) {
        int w = ws[lane];
#pragma unroll
        for (int off = 1; off < 32; off <<= 1) {
            int t = __shfl_up_sync(0xffffffffu, w, off);
            if (lane >= off) w += t;
        }
        ws[lane] = w;
    }
    __syncthreads();
    int base = (wid > 0) ? ws[wid - 1] : 0;
    if (i < Nn) rowptr[i] = base + x - v;
    if (threadIdx.x == 1023) bsum[blockIdx.x] = base + x;
}

__global__ void scan2_kernel(const int* __restrict__ bsum, int* __restrict__ bscan, int NB) {
    __shared__ int ws[4];
    int tid = threadIdx.x, lane = tid & 31, wid = tid >> 5;
    int v = (tid < NB) ? bsum[tid] : 0;
    int x = v;
#pragma unroll
    for (int off = 1; off < 32; off <<= 1) {
        int t = __shfl_up_sync(0xffffffffu, x, off);
        if (lane >= off) x += t;
    }
    if (lane == 31) ws[wid] = x;
    __syncthreads();
    int base = 0;
    for (int t = 0; t < wid; t++) base += ws[t];
    if (tid < NB) bscan[tid] = base + x - v;
}

__global__ void scan3_kernel(int* __restrict__ rowptr, const int* __restrict__ bscan,
                             int Nn, int E) {
    int i = blockIdx.x * blockDim.x + threadIdx.x;
    if (i < Nn) rowptr[i] += bscan[i >> 10];
    if (i == 0) rowptr[Nn] = E;
}

__global__ void fill_kernel(const int* __restrict__ ei, int E,
                            const int* __restrict__ rowptr, int* __restrict__ fill,
                            int* __restrict__ colA) {
    int e = blockIdx.x * blockDim.x + threadIdx.x;
    if (e < E) {
        int src = ei[e];
        int dst = ei[E + e];
        int pos = atomicAdd(&fill[dst], 1);
        colA[rowptr[dst] + pos] = src;
    }
}

// weight prep: bf16 split + pack pairs along k; output n-major [n][K2]
__global__ void prep_w_kernel(const float* __restrict__ W, uint32_t* __restrict__ Hi,
                              uint32_t* __restrict__ Lo, int K2) {
    int idx = blockIdx.x * blockDim.x + threadIdx.x;
    if (idx < K2 * 128) {
        int n = idx / K2, kp = idx - n * K2;
        float v0 = W[(size_t)(2 * kp) * 128 + n];
        float v1 = W[(size_t)(2 * kp + 1) * 128 + n];
        uint32_t hi, lo;
        split2(v0, v1, hi, lo);
        Hi[idx] = hi;
        Lo[idx] = lo;
    }
}

// ---------------- bf16x3 split mma.sync GEMM, cp.async + ldmatrix ----------------
// grid (ceil(N/128), 2): y=0 -> Cq (half2) = A@Wl ; y=1 -> Cr (fp32) = A@Wr + b
// BM=128, BN=128, BK=32 (16 k-pairs); 8 warps 4(m)x2(n); warp tile 32x64; m16n8k16 x3.
#define LDP    20                     // padded stride (conflict-free for ldmatrix row groups)
#define A_U    (128 * LDP)            // 2560
#define W_U    (128 * LDP)            // 2560
#define STAGE_U (2 * A_U + 2 * W_U)   // 10240 uint32 = 40960 B
#define GSMEM  (2 * STAGE_U * 4)      // 81920 bytes

__device__ __forceinline__ void mma_bf16(float* d, const uint32_t* a, uint32_t b0, uint32_t b1) {
    asm volatile(
        "mma.sync.aligned.m16n8k16.row.col.f32.bf16.bf16.f32 "
        "{%0,%1,%2,%3}, {%4,%5,%6,%7}, {%8,%9}, {%0,%1,%2,%3};"
        : "+f"(d[0]), "+f"(d[1]), "+f"(d[2]), "+f"(d[3])
        : "r"(a[0]), "r"(a[1]), "r"(a[2]), "r"(a[3]), "r"(b0), "r"(b1));
}

__global__ void __launch_bounds__(256, 2) mma_gemm_kernel(
    const uint32_t* __restrict__ Agh, const uint32_t* __restrict__ Agl, int K2,
    const uint32_t* __restrict__ Wlh, const uint32_t* __restrict__ Wll,
    const uint32_t* __restrict__ Wrh, const uint32_t* __restrict__ Wrl,
    const float* __restrict__ bias,
    uint32_t* __restrict__ Cq, float* __restrict__ Cr, int Nn)
{
    extern __shared__ uint32_t smu[];
    uint32_t sbase = smem_u32(smu);

    const uint32_t* Wgh = (blockIdx.y == 0) ? Wlh : Wrh;
    const uint32_t* Wgl = (blockIdx.y == 0) ? Wll : Wrl;
    const bool isRoot = (blockIdx.y == 1);

    int tid = threadIdx.x, lane = tid & 31, wid = tid >> 5;
    int wm = wid >> 1, wn = wid & 1;
    int row0 = blockIdx.x * 128;

    float acc[2][8][4];
#pragma unroll
    for (int mt = 0; mt < 2; mt++)
#pragma unroll
        for (int nt = 0; nt < 8; nt++)
#pragma unroll
            for (int j = 0; j < 4; j++) acc[mt][nt][j] = 0.0f;

    int rq = lane >> 2;
    const int NC = K2 >> 4;   // chunks of 16 k-pairs (BK=32)

    // per-lane ldmatrix address components (uint32-offset units)
    int aRow = wm * 32 + (lane & 15);            // + mt*16
    int aCol = (lane >> 4) * 4;                  // + kb2
    int wRow = wn * 64 + (lane & 7) + ((lane >> 4) & 1) * 8;  // + ntp*16
    int wCol = ((lane >> 3) & 1) * 4;            // + kb2

    auto loadStage = [&](int i) {
        int st = i & 1;
        int kc2 = i << 4;
        uint32_t sa = sbase + (uint32_t)(st * STAGE_U) * 4;
        uint32_t sw = sa + (uint32_t)(2 * A_U) * 4;
#pragma unroll
        for (int it = 0; it < 2; it++) {
            int lin = tid + it * 256;
            int r = lin >> 2, c = (lin & 3) * 4;
            int gr = row0 + r;
            cpa16(sa + (uint32_t)(r * LDP + c) * 4, Agh + (size_t)gr * K2 + kc2 + c, gr < Nn);
            cpa16(sa + (uint32_t)(A_U + r * LDP + c) * 4, Agl + (size_t)gr * K2 + kc2 + c, gr < Nn);
        }
#pragma unroll
        for (int it = 0; it < 2; it++) {
            int lin = tid + it * 256;
            int n = lin >> 2, c = (lin & 3) * 4;
            cpa16(sw + (uint32_t)(n * LDP + c) * 4, Wgh + (size_t)n * K2 + kc2 + c, true);
            cpa16(sw + (uint32_t)(W_U + n * LDP + c) * 4, Wgl + (size_t)n * K2 + kc2 + c, true);
        }
    };

    loadStage(0);
    cpa_commit();

    for (int i = 0; i < NC; i++) {
        if (i + 1 < NC) {
            loadStage(i + 1);
            cpa_commit();
            cpa_wait<1>();
        } else {
            cpa_wait<0>();
        }
        __syncthreads();

        uint32_t sa = sbase + (uint32_t)((i & 1) * STAGE_U) * 4;
        uint32_t sw = sa + (uint32_t)(2 * A_U) * 4;

#pragma unroll
        for (int ks = 0; ks < 2; ks++) {
            int kb2 = ks * 8;
            uint32_t ah[2][4], al[2][4];
#pragma unroll
            for (int mt = 0; mt < 2; mt++) {
                uint32_t aaddr = sa + (uint32_t)(((aRow + mt * 16) * LDP) + kb2 + aCol) * 4;
                ldsm_x4(ah[mt][0], ah[mt][1], ah[mt][2], ah[mt][3], aaddr);
                ldsm_x4(al[mt][0], al[mt][1], al[mt][2], al[mt][3], aaddr + A_U * 4);
            }
            uint32_t bh[8][2], bl[8][2];
#pragma unroll
            for (int ntp = 0; ntp < 4; ntp++) {
                uint32_t waddr = sw + (uint32_t)(((wRow + ntp * 16) * LDP) + kb2 + wCol) * 4;
                ldsm_x4(bh[2 * ntp][0], bh[2 * ntp][1], bh[2 * ntp + 1][0], bh[2 * ntp + 1][1], waddr);
                ldsm_x4(bl[2 * ntp][0], bl[2 * ntp][1], bl[2 * ntp + 1][0], bl[2 * ntp + 1][1],
                        waddr + W_U * 4);
            }
#pragma unroll
            for (int nt = 0; nt < 8; nt++) {
#pragma unroll
                for (int mt = 0; mt < 2; mt++) {
                    mma_bf16(acc[mt][nt], ah[mt], bh[nt][0], bh[nt][1]);
                    mma_bf16(acc[mt][nt], ah[mt], bl[nt][0], bl[nt][1]);
                    mma_bf16(acc[mt][nt], al[mt], bh[nt][0], bh[nt][1]);
                }
            }
        }
        __syncthreads();
    }

    // epilogue
    int c2 = (lane & 3) * 2;
#pragma unroll
    for (int mt = 0; mt < 2; mt++) {
#pragma unroll
        for (int nt = 0; nt < 8; nt++) {
            int gc = wn * 64 + nt * 8 + c2;
            int gr0 = row0 + wm * 32 + mt * 16 + rq;
            int gr1 = gr0 + 8;
            if (isRoot) {
                float bv0 = bias[gc], bv1 = bias[gc + 1];
                if (gr0 < Nn) {
                    float2 v = make_float2(acc[mt][nt][0] + bv0, acc[mt][nt][1] + bv1);
                    *(float2*)&Cr[(size_t)gr0 * 128 + gc] = v;
                }
                if (gr1 < Nn) {
                    float2 v = make_float2(acc[mt][nt][2] + bv0, acc[mt][nt][3] + bv1);
                    *(float2*)&Cr[(size_t)gr1 * 128 + gc] = v;
                }
            } else {
                if (gr0 < Nn) {
                    __half2 hv = __floats2half2_rn(acc[mt][nt][0], acc[mt][nt][1]);
                    Cq[(size_t)gr0 * 64 + (gc >> 1)] = *(uint32_t*)&hv;
                }
                if (gr1 < Nn) {
                    __half2 hv = __floats2half2_rn(acc[mt][nt][2], acc[mt][nt][3]);
                    Cq[(size_t)gr1 * 64 + (gc >> 1)] = *(uint32_t*)&hv;
                }
            }
        }
    }
}

// ---------------- CSR mean-aggregation (common gather body) ----------------
__device__ __forceinline__ float4 agg_gather(const uint32_t* __restrict__ Cq,
                                             const float* __restrict__ Cr,
                                             const int* __restrict__ rowptr,
                                             const int* __restrict__ colA,
                                             int warp, int lane) {
    int beg = rowptr[warp], end = rowptr[warp + 1];
    float4 acc0 = make_float4(0.f, 0.f, 0.f, 0.f);
    float4 acc1 = make_float4(0.f, 0.f, 0.f, 0.f);
    int j = beg;
    for (; j + 1 < end; j += 2) {
        int s0 = colA[j], s1 = colA[j + 1];
        uint2 u0 = *(const uint2*)&Cq[(size_t)s0 * 64 + lane * 2];
        uint2 u1 = *(const uint2*)&Cq[(size_t)s1 * 64 + lane * 2];
        float2 a0 = __half22float2(*(__half2*)&u0.x);
        float2 b0 = __half22float2(*(__half2*)&u0.y);
        float2 a1 = __half22float2(*(__half2*)&u1.x);
        float2 b1 = __half22float2(*(__half2*)&u1.y);
        acc0.x += a0.x; acc0.y += a0.y; acc0.z += b0.x; acc0.w += b0.y;
        acc1.x += a1.x; acc1.y += a1.y; acc1.z += b1.x; acc1.w += b1.y;
    }
    if (j < end) {
        int s = colA[j];
        uint2 u = *(const uint2*)&Cq[(size_t)s * 64 + lane * 2];
        float2 a = __half22float2(*(__half2*)&u.x);
        float2 b = __half22float2(*(__half2*)&u.y);
        acc0.x += a.x; acc0.y += a.y; acc0.z += b.x; acc0.w += b.y;
    }
    float inv = 1.0f / fmaxf((float)(end - beg), 1.0f);
    float4 r = *(const float4*)&Cr[(size_t)warp * 128 + lane * 4];
    float4 o;
    o.x = (acc0.x + acc1.x) * inv + r.x;
    o.y = (acc0.y + acc1.y) * inv + r.y;
    o.z = (acc0.z + acc1.z) * inv + r.z;
    o.w = (acc0.w + acc1.w) * inv + r.w;
    return o;
}

// layers 0/1: emit only the relu+bf16-split input for the next GEMM
__global__ void agg_mid_kernel(const uint32_t* __restrict__ Cq, const float* __restrict__ Cr,
                               const int* __restrict__ rowptr, const int* __restrict__ colA,
                               uint32_t* __restrict__ Ahh, uint32_t* __restrict__ Ahl, int Nn) {
    int warp = (blockIdx.x * blockDim.x + threadIdx.x) >> 5;
    int lane = threadIdx.x & 31;
    if (warp >= Nn) return;
    float4 o = agg_gather(Cq, Cr, rowptr, colA, warp, lane);
    float r0 = fmaxf(o.x, 0.f), r1 = fmaxf(o.y, 0.f);
    float r2 = fmaxf(o.z, 0.f), r3v = fmaxf(o.w, 0.f);
    uint32_t h0, l0, h1, l1;
    split2(r0, r1, h0, l0);
    split2(r2, r3v, h1, l1);
    size_t pb = (size_t)warp * 64 + lane * 2;
    *(uint2*)&Ahh[pb] = make_uint2(h0, h1);
    *(uint2*)&Ahl[pb] = make_uint2(l0, l1);
}

// layer 2: fuse relu + layer-3 dual dot products; emit p and r3 only
__global__ void agg_last_kernel(const uint32_t* __restrict__ Cq, const float* __restrict__ Cr,
                                const int* __restrict__ rowptr, const int* __restrict__ colA,
                                const float* __restrict__ Wl3, const float* __restrict__ Wr3,
                                const float* __restrict__ b3,
                                float* __restrict__ p, float* __restrict__ r3, int Nn) {
    int warp = (blockIdx.x * blockDim.x + threadIdx.x) >> 5;
    int lane = threadIdx.x & 31;
    if (warp >= Nn) return;
    float4 o = agg_gather(Cq, Cr, rowptr, colA, warp, lane);
    o.x = fmaxf(o.x, 0.f); o.y = fmaxf(o.y, 0.f);
    o.z = fmaxf(o.z, 0.f); o.w = fmaxf(o.w, 0.f);
    float4 wl = *(const float4*)&Wl3[lane * 4];
    float4 wr = *(const float4*)&Wr3[lane * 4];
    float sl = o.x * wl.x + o.y * wl.y + o.z * wl.z + o.w * wl.w;
    float sr = o.x * wr.x + o.y * wr.y + o.z * wr.z + o.w * wr.w;
#pragma unroll
    for (int off = 16; off; off >>= 1) {
        sl += __shfl_down_sync(0xffffffffu, sl, off);
        sr += __shfl_down_sync(0xffffffffu, sr, off);
    }
    if (lane == 0) { p[warp] = sl; r3[warp] = sr + b3[0]; }
}

// ---------------- layer 3 scalar aggregation + sigmoid + mean ----------------
__global__ void l3_agg_kernel(const float* __restrict__ p, const float* __restrict__ r3,
                              const int* __restrict__ rowptr, const int* __restrict__ colA,
                              float* __restrict__ out, float* __restrict__ gsum, int Nn) {
    int warp = (blockIdx.x * blockDim.x + threadIdx.x) >> 5;
    int lane = threadIdx.x & 31;
    int wInBlk = threadIdx.x >> 5;
    float val = 0.f;
    if (warp < Nn) {
        int beg = rowptr[warp], end = rowptr[warp + 1];
        float s = 0.f;
        for (int j = beg + lane; j < end; j += 32) s += p[colA[j]];
#pragma unroll
        for (int off = 16; off; off >>= 1) s += __shfl_down_sync(0xffffffffu, s, off);
        if (lane == 0) {
            float z = s / fmaxf((float)(end - beg), 1.0f) + r3[warp];
            val = 1.0f / (1.0f + expf(-z));
            out[warp] = val;
        }
    }
    __shared__ float sh[8];
    if (lane == 0) sh[wInBlk] = val;
    __syncthreads();
    if (threadIdx.x < 8) {
        float v = sh[threadIdx.x];
#pragma unroll
        for (int off = 4; off; off >>= 1) v += __shfl_down_sync(0x000000ffu, v, off);
        if (threadIdx.x == 0) atomicAdd(gsum, v);
    }
}

__global__ void finalize_kernel(float* __restrict__ out, const float* __restrict__ gsum,
                                int Nn, int out_size) {
    if (out_size > Nn) out[out_size - 1] = gsum[0] / (float)Nn;
}

// ---------------- launch ----------------
extern "C" void kernel_launch(void* const* d_in, const int* in_sizes, int n_in,
                              void* d_out, int out_size) {
    const float* x    = (const float*)d_in[0];
    const float* diff = (const float*)d_in[1];
    const float* rec  = (const float*)d_in[2];
    const float* hid  = (const float*)d_in[3];
    const int*   ei   = (const int*)d_in[4];
    const float* Wl0 = (const float*)d_in[5];
    const float* Wr0 = (const float*)d_in[6];
    const float* b0  = (const float*)d_in[7];
    const float* Wl1 = (const float*)d_in[8];
    const float* Wr1 = (const float*)d_in[9];
    const float* b1  = (const float*)d_in[10];
    const float* Wl2 = (const float*)d_in[11];
    const float* Wr2 = (const float*)d_in[12];
    const float* b2  = (const float*)d_in[13];
    const float* Wl3 = (const float*)d_in[14];
    const float* Wr3 = (const float*)d_in[15];
    const float* b3  = (const float*)d_in[16];
    float* out = (float*)d_out;

    int Nn = in_sizes[0] / 64;
    int E  = in_sizes[4] / 2;

    float *Cr, *p, *r3, *gsum;
    uint32_t *A0h, *A0l, *Ahh, *Ahl, *Cq, *W0, *W1, *W2;
    int *rowptr, *colA, *cnt, *fill, *bsum, *bscan;
    cudaGetSymbolAddress((void**)&A0h, g_A0h);
    cudaGetSymbolAddress((void**)&A0l, g_A0l);
    cudaGetSymbolAddress((void**)&Ahh, g_Ahh);
    cudaGetSymbolAddress((void**)&Ahl, g_Ahl);
    cudaGetSymbolAddress((void**)&Cq, g_Cq);
    cudaGetSymbolAddress((void**)&Cr, g_Cr);
    cudaGetSymbolAddress((void**)&rowptr, g_rowptr);
    cudaGetSymbolAddress((void**)&colA, g_col);
    cudaGetSymbolAddress((void**)&cnt, g_cnt);
    cudaGetSymbolAddress((void**)&fill, g_fill);
    cudaGetSymbolAddress((void**)&bsum, g_bsum);
    cudaGetSymbolAddress((void**)&bscan, g_bscan);
    cudaGetSymbolAddress((void**)&p, g_p);
    cudaGetSymbolAddress((void**)&r3, g_r3);
    cudaGetSymbolAddress((void**)&gsum, g_sum);
    cudaGetSymbolAddress((void**)&W0, g_W0);
    cudaGetSymbolAddress((void**)&W1, g_W1);
    cudaGetSymbolAddress((void**)&W2, g_W2);

    cudaFuncSetAttribute(mma_gemm_kernel, cudaFuncAttributeMaxDynamicSharedMemorySize, GSMEM);

    int threads = 256;
    int NB = (Nn + 1023) / 1024;
    const int P0 = 128 * 128;   // uint32 per L0 weight matrix half
    const int P1 = 128 * 64;
    int grX = (Nn + 127) / 128;
    int aggBlocks = (Nn + 7) / 8;

    // Launch order: 4th launch (ncu-profiled) is the L0 GEMM.
    concat_kernel<<<(Nn * 128 + threads - 1) / threads, threads>>>(x, diff, rec, hid, A0h, A0l, Nn);  // 1
    prep_w_kernel<<<(P0 + 255) / 256, 256>>>(Wl0, W0 + 0 * P0, W0 + 1 * P0, 128);                     // 2
    prep_w_kernel<<<(P0 + 255) / 256, 256>>>(Wr0, W0 + 2 * P0, W0 + 3 * P0, 128);                     // 3
    mma_gemm_kernel<<<dim3(grX, 2), 256, GSMEM>>>(A0h, A0l, 128, W0 + 0 * P0, W0 + 1 * P0,
                                                  W0 + 2 * P0, W0 + 3 * P0, b0, Cq, Cr, Nn);           // 4 <- profiled
    // CSR build
    zero_kernel<<<256, threads>>>(cnt, fill, gsum, Nn);
    count_kernel<<<(E + threads - 1) / threads, threads>>>(ei, E, cnt);
    scan1_kernel<<<NB, 1024>>>(cnt, rowptr, bsum, Nn);
    scan2_kernel<<<1, 128>>>(bsum, bscan, NB);
    scan3_kernel<<<(Nn + threads - 1) / threads, threads>>>(rowptr, bscan, Nn, E);
    fill_kernel<<<(E + threads - 1) / threads, threads>>>(ei, E, rowptr, fill, colA);
    // remaining weight prep
    prep_w_kernel<<<(P1 + 255) / 256, 256>>>(Wl1, W1 + 0 * P1, W1 + 1 * P1, 64);
    prep_w_kernel<<<(P1 + 255) / 256, 256>>>(Wr1, W1 + 2 * P1, W1 + 3 * P1, 64);
    prep_w_kernel<<<(P1 + 255) / 256, 256>>>(Wl2, W2 + 0 * P1, W2 + 1 * P1, 64);
    prep_w_kernel<<<(P1 + 255) / 256, 256>>>(Wr2, W2 + 2 * P1, W2 + 3 * P1, 64);

    agg_mid_kernel<<<aggBlocks, 256>>>(Cq, Cr, rowptr, colA, Ahh, Ahl, Nn);

    mma_gemm_kernel<<<dim3(grX, 2), 256, GSMEM>>>(Ahh, Ahl, 64, W1 + 0 * P1, W1 + 1 * P1,
                                                  W1 + 2 * P1, W1 + 3 * P1, b1, Cq, Cr, Nn);
    agg_mid_kernel<<<aggBlocks, 256>>>(Cq, Cr, rowptr, colA, Ahh, Ahl, Nn);

    mma_gemm_kernel<<<dim3(grX, 2), 256, GSMEM>>>(Ahh, Ahl, 64, W2 + 0 * P1, W2 + 1 * P1,
                                                  W2 + 2 * P1, W2 + 3 * P1, b2, Cq, Cr, Nn);
    agg_last_kernel<<<aggBlocks, 256>>>(Cq, Cr, rowptr, colA, Wl3, Wr3, b3, p, r3, Nn);

    l3_agg_kernel<<<aggBlocks, 256>>>(p, r3, rowptr, colA, out, gsum, Nn);
    finalize_kernel<<<1, 1>>>(out, gsum, Nn, out_size);
}